// round 16
// baseline (speedup 1.0000x reference)
#include <cuda_runtime.h>
#include <cuda_fp16.h>

#define N_NODES  50000
#define N_EDGES  800000
#define N_GRAPHS 64
#define HID      64

#define CHUNK 256
#define NBLK ((N_NODES + CHUNK - 1) / CHUNK)   // 196

// ---------------- scratch (device globals; no allocation) ----------------
__device__ int    g_in_deg[N_NODES];
__device__ int    g_out_deg[N_NODES];
__device__ float  g_norm_src[N_NODES];
__device__ float  g_norm_dst[N_NODES];
__device__ float  g_h0n[N_NODES];         // in_deg * norm_src
__device__ float  g_x0[N_NODES];          // raw layer-0 aggregate (filled in k_bucket)
__device__ float2 g_xn[N_NODES];          // (x0_v * nd_v * ns_v, ns_v)
__device__ int    g_row_off[N_NODES + 1];
__device__ int    g_cursor[N_NODES];
__device__ int    g_edge_src[N_EDGES];
__device__ float  g_hA[N_NODES * HID];    // layer-2 output (fp32)
__device__ __half g_hBh[N_NODES * HID];   // layer-1 output, pre-scaled by norm_src, fp16
__device__ float  g_hg[N_GRAPHS * HID];
__device__ float  g_cnt[N_GRAPHS];
__device__ int    g_part[NBLK];

// ---------------- init ----------------
__global__ void k_zero() {
    int i = blockIdx.x * blockDim.x + threadIdx.x;
    if (i < N_NODES) { g_in_deg[i] = 0; g_out_deg[i] = 0; g_x0[i] = 0.f; }
    if (i < N_GRAPHS * HID) g_hg[i] = 0.f;
    if (i < N_GRAPHS) g_cnt[i] = 0.f;
}

__global__ void k_deg(const int* __restrict__ src, const int* __restrict__ dst) {
    int i = blockIdx.x * blockDim.x + threadIdx.x;
    if (i < N_EDGES) {
        atomicAdd(&g_in_deg[dst[i]], 1);
        atomicAdd(&g_out_deg[src[i]], 1);
    }
}

// ---------------- prep: norms + h0n + per-block partial sums ----------------
__global__ void k_prep() {
    __shared__ int s[CHUNK];
    int t = threadIdx.x;
    int idx = blockIdx.x * CHUNK + t;
    int id = 0;
    if (idx < N_NODES) {
        id = g_in_deg[idx];
        int od = g_out_deg[idx];
        float ns = rsqrtf((float)(od > 1 ? od : 1));
        g_norm_dst[idx] = rsqrtf((float)(id > 1 ? id : 1));
        g_norm_src[idx] = ns;
        g_h0n[idx] = (float)id * ns;
    }
    s[t] = id;
    __syncthreads();
    #pragma unroll
    for (int off = CHUNK / 2; off > 0; off >>= 1) {
        if (t < off) s[t] += s[t + off];
        __syncthreads();
    }
    if (t == 0) g_part[blockIdx.x] = s[0];
    if (idx == 0) g_row_off[N_NODES] = N_EDGES;
}

// ---------------- offsets: block prefix (reduce partials below) + local scan ----------------
__global__ void k_offsets() {
    __shared__ int sp[CHUNK];
    __shared__ int s[CHUNK];
    int t = threadIdx.x;
    int bid = blockIdx.x;

    sp[t] = (t < bid) ? g_part[t] : 0;
    __syncthreads();
    #pragma unroll
    for (int off = CHUNK / 2; off > 0; off >>= 1) {
        if (t < off) sp[t] += sp[t + off];
        __syncthreads();
    }
    int blockpre = sp[0];

    int idx = bid * CHUNK + t;
    int my = (idx < N_NODES) ? g_in_deg[idx] : 0;
    s[t] = my;
    __syncthreads();
    #pragma unroll
    for (int off = 1; off < CHUNK; off <<= 1) {
        int v = (t >= off) ? s[t - off] : 0;
        __syncthreads();
        s[t] += v;
        __syncthreads();
    }
    if (idx < N_NODES) {
        int ex = s[t] - my + blockpre;   // exclusive prefix
        g_row_off[idx] = ex;
        g_cursor[idx]  = ex;
    }
}

// ---------------- bucket edges by dst + fused layer-0 scalar aggregation ----------------
__global__ void k_bucket(const int* __restrict__ src, const int* __restrict__ dst) {
    int i = blockIdx.x * blockDim.x + threadIdx.x;
    if (i < N_EDGES) {
        int s = src[i];
        int d = dst[i];
        int p = atomicAdd(&g_cursor[d], 1);
        g_edge_src[p] = s;
        atomicAdd(&g_x0[d], g_h0n[s]);   // fused: x0 aggregate, no separate gather pass
    }
}

// ---------------- finalize rank-1 state: (x0*nd*ns, ns) ----------------
__global__ void k_xn() {
    int i = blockIdx.x * blockDim.x + threadIdx.x;
    if (i < N_NODES) {
        float x  = g_x0[i] * g_norm_dst[i];
        float ns = g_norm_src[i];
        float2 p; p.x = x * ns; p.y = ns;
        g_xn[i] = p;
    }
}

// ---------------- layer 1: rank-1 on-the-fly gather + fused 64x64 matvec ----------------
// per-edge message_f = max((x_s*ns_s)*W0_f + b0_f*ns_s, 0); 8B broadcast load per edge.
// output row pre-scaled by norm_src[v], stored fp16 for layer 2.
__global__ void __launch_bounds__(256) k_layer1(const float* __restrict__ W0,
                                                const float* __restrict__ b0,
                                                const float* __restrict__ W1,
                                                const float* __restrict__ b1) {
    __shared__ float sW[HID * HID];
    __shared__ float sb[HID];
    __shared__ float xs[8][HID];

    int tid = threadIdx.x;
    for (int i = tid; i < HID * HID; i += 256) sW[i] = W1[i];
    if (tid < HID) sb[tid] = b1[tid];
    __syncthreads();

    int wib = tid >> 5;
    int lane = tid & 31;
    int v = blockIdx.x * 8 + wib;

    float w0a = W0[2 * lane], w0b = W0[2 * lane + 1];
    float b0a = b0[2 * lane], b0b = b0[2 * lane + 1];

    if (v < N_NODES) {
        int beg = g_row_off[v], end = g_row_off[v + 1];
        float a0 = 0.f, a1 = 0.f;
        int e = beg;
        for (; e + 4 <= end; e += 4) {
            int s0 = g_edge_src[e];
            int s1 = g_edge_src[e + 1];
            int s2 = g_edge_src[e + 2];
            int s3 = g_edge_src[e + 3];
            float2 p0 = g_xn[s0];
            float2 p1 = g_xn[s1];
            float2 p2 = g_xn[s2];
            float2 p3 = g_xn[s3];
            a0 += fmaxf(fmaf(p0.x, w0a, b0a * p0.y), 0.f)
                + fmaxf(fmaf(p1.x, w0a, b0a * p1.y), 0.f)
                + fmaxf(fmaf(p2.x, w0a, b0a * p2.y), 0.f)
                + fmaxf(fmaf(p3.x, w0a, b0a * p3.y), 0.f);
            a1 += fmaxf(fmaf(p0.x, w0b, b0b * p0.y), 0.f)
                + fmaxf(fmaf(p1.x, w0b, b0b * p1.y), 0.f)
                + fmaxf(fmaf(p2.x, w0b, b0b * p2.y), 0.f)
                + fmaxf(fmaf(p3.x, w0b, b0b * p3.y), 0.f);
        }
        for (; e < end; e++) {
            float2 p = g_xn[g_edge_src[e]];
            a0 += fmaxf(fmaf(p.x, w0a, b0a * p.y), 0.f);
            a1 += fmaxf(fmaf(p.x, w0b, b0b * p.y), 0.f);
        }
        float nd = g_norm_dst[v];
        xs[wib][2 * lane]     = a0 * nd;
        xs[wib][2 * lane + 1] = a1 * nd;
    }
    __syncwarp();

    if (v < N_NODES) {
        float o0 = sb[2 * lane], o1 = sb[2 * lane + 1];
        #pragma unroll
        for (int i = 0; i < HID; i++) {
            float xi = xs[wib][i];
            float2 w = *(const float2*)&sW[i * HID + 2 * lane];
            o0 = fmaf(xi, w.x, o0);
            o1 = fmaf(xi, w.y, o1);
        }
        float ns = g_norm_src[v];           // pre-scale for layer 2
        float r0 = fmaxf(o0, 0.f) * ns;     // >= 0: fp16 rel error <= 4.9e-4
        float r1 = fmaxf(o1, 0.f) * ns;
        __half2 h2 = __floats2half2_rn(r0, r1);
        *(__half2*)&g_hBh[v * HID + 2 * lane] = h2;
    }
}

// ---------------- layer 2: oct-per-node fp16 gather + fused matvec ----------------
// 8 lanes per node; lane owns features 8*sub .. 8*sub+7 (one uint4 = 8 halves).
// 4 nodes per warp -> 4 independent edge chains; unroll-4 batched index loads.
__global__ void __launch_bounds__(256) k_layer2(const float* __restrict__ W2,
                                                const float* __restrict__ b2) {
    __shared__ float sW[HID * HID];
    __shared__ float sb[HID];
    __shared__ float xs[32][HID + 4];   // pad: octs hit different banks

    int tid = threadIdx.x;
    for (int i = tid; i < HID * HID; i += 256) sW[i] = W2[i];
    if (tid < HID) sb[tid] = b2[tid];
    __syncthreads();

    int oct = tid >> 3;        // 0..31 nodes per block
    int sub = tid & 7;         // lane in oct
    int v = blockIdx.x * 32 + oct;

    if (v < N_NODES) {
        int beg = g_row_off[v], end = g_row_off[v + 1];
        float2 a0 = make_float2(0.f, 0.f);
        float2 a1 = make_float2(0.f, 0.f);
        float2 a2 = make_float2(0.f, 0.f);
        float2 a3 = make_float2(0.f, 0.f);
        const __half2* hb = (const __half2*)g_hBh;
        int e = beg;
        for (; e + 4 <= end; e += 4) {
            int s0 = g_edge_src[e];
            int s1 = g_edge_src[e + 1];
            int s2 = g_edge_src[e + 2];
            int s3 = g_edge_src[e + 3];
            uint4 r0 = *(const uint4*)&hb[s0 * (HID / 2) + 4 * sub];
            uint4 r1 = *(const uint4*)&hb[s1 * (HID / 2) + 4 * sub];
            uint4 r2 = *(const uint4*)&hb[s2 * (HID / 2) + 4 * sub];
            uint4 r3 = *(const uint4*)&hb[s3 * (HID / 2) + 4 * sub];
            #pragma unroll
            for (int k = 0; k < 4; k++) {
                uint4 r = (k == 0) ? r0 : (k == 1) ? r1 : (k == 2) ? r2 : r3;
                float2 f0 = __half22float2(*(__half2*)&r.x);
                float2 f1 = __half22float2(*(__half2*)&r.y);
                float2 f2 = __half22float2(*(__half2*)&r.z);
                float2 f3 = __half22float2(*(__half2*)&r.w);
                a0.x += f0.x; a0.y += f0.y;
                a1.x += f1.x; a1.y += f1.y;
                a2.x += f2.x; a2.y += f2.y;
                a3.x += f3.x; a3.y += f3.y;
            }
        }
        for (; e < end; e++) {
            int s = g_edge_src[e];
            uint4 r = *(const uint4*)&hb[s * (HID / 2) + 4 * sub];
            float2 f0 = __half22float2(*(__half2*)&r.x);
            float2 f1 = __half22float2(*(__half2*)&r.y);
            float2 f2 = __half22float2(*(__half2*)&r.z);
            float2 f3 = __half22float2(*(__half2*)&r.w);
            a0.x += f0.x; a0.y += f0.y;
            a1.x += f1.x; a1.y += f1.y;
            a2.x += f2.x; a2.y += f2.y;
            a3.x += f3.x; a3.y += f3.y;
        }
        float nd = g_norm_dst[v];
        float* xr = &xs[oct][8 * sub];
        xr[0] = a0.x * nd; xr[1] = a0.y * nd;
        xr[2] = a1.x * nd; xr[3] = a1.y * nd;
        xr[4] = a2.x * nd; xr[5] = a2.y * nd;
        xr[6] = a3.x * nd; xr[7] = a3.y * nd;
    }
    __syncwarp();

    if (v < N_NODES) {
        float o[8];
        #pragma unroll
        for (int j = 0; j < 8; j++) o[j] = sb[8 * sub + j];
        #pragma unroll
        for (int i = 0; i < HID; i++) {
            float xi = xs[oct][i];
            float4 wa = *(const float4*)&sW[i * HID + 8 * sub];
            float4 wb = *(const float4*)&sW[i * HID + 8 * sub + 4];
            o[0] = fmaf(xi, wa.x, o[0]);
            o[1] = fmaf(xi, wa.y, o[1]);
            o[2] = fmaf(xi, wa.z, o[2]);
            o[3] = fmaf(xi, wa.w, o[3]);
            o[4] = fmaf(xi, wb.x, o[4]);
            o[5] = fmaf(xi, wb.y, o[5]);
            o[6] = fmaf(xi, wb.z, o[6]);
            o[7] = fmaf(xi, wb.w, o[7]);
        }
        float4 oa, ob;
        oa.x = fmaxf(o[0], 0.f); oa.y = fmaxf(o[1], 0.f);
        oa.z = fmaxf(o[2], 0.f); oa.w = fmaxf(o[3], 0.f);
        ob.x = fmaxf(o[4], 0.f); ob.y = fmaxf(o[5], 0.f);
        ob.z = fmaxf(o[6], 0.f); ob.w = fmaxf(o[7], 0.f);
        *(float4*)&g_hA[v * HID + 8 * sub]     = oa;
        *(float4*)&g_hA[v * HID + 8 * sub + 4] = ob;
    }
}

// ---------------- graph pooling: sorted node2graph run-length flush ----------------
#define NODES_PER_WARP 64
#define POOL_WARPS ((N_NODES + NODES_PER_WARP - 1) / NODES_PER_WARP)   // 782

__global__ void k_pool(const int* __restrict__ n2g) {
    int gtid = blockIdx.x * blockDim.x + threadIdx.x;
    int w = gtid >> 5;
    int lane = gtid & 31;
    if (w >= POOL_WARPS) return;

    int v0 = w * NODES_PER_WARP;
    int v1 = v0 + NODES_PER_WARP; if (v1 > N_NODES) v1 = N_NODES;

    int   cur = n2g[v0];
    float a0 = 0.f, a1 = 0.f;
    float cnt = 0.f;

    for (int v = v0; v < v1; v++) {
        int g = n2g[v];
        if (g != cur) {
            atomicAdd(&g_hg[cur * HID + 2 * lane],     a0);
            atomicAdd(&g_hg[cur * HID + 2 * lane + 1], a1);
            if (lane == 0) atomicAdd(&g_cnt[cur], cnt);
            cur = g; a0 = 0.f; a1 = 0.f; cnt = 0.f;
        }
        float2 hv = *(const float2*)&g_hA[v * HID + 2 * lane];
        a0 += hv.x;
        a1 += hv.y;
        cnt += 1.f;
    }
    atomicAdd(&g_hg[cur * HID + 2 * lane],     a0);
    atomicAdd(&g_hg[cur * HID + 2 * lane + 1], a1);
    if (lane == 0) atomicAdd(&g_cnt[cur], cnt);
}

// ---------------- readout ----------------
__global__ void k_out(const float* __restrict__ Wr, const float* __restrict__ br,
                      float* __restrict__ out) {
    int gtid = blockIdx.x * blockDim.x + threadIdx.x;
    int g = gtid >> 5;
    int lane = gtid & 31;
    if (g >= N_GRAPHS) return;
    float inv = 1.f / fmaxf(g_cnt[g], 1.f);
    float2 hv = *(const float2*)&g_hg[g * HID + 2 * lane];
    float2 wr = *(const float2*)&Wr[2 * lane];
    float acc = hv.x * inv * wr.x + hv.y * inv * wr.y;
    #pragma unroll
    for (int off = 16; off; off >>= 1) acc += __shfl_xor_sync(0xffffffffu, acc, off);
    if (lane == 0) out[g] = acc + br[0];
}

// ---------------- launch ----------------
extern "C" void kernel_launch(void* const* d_in, const int* in_sizes, int n_in,
                              void* d_out, int out_size) {
    const int*   src = (const int*)d_in[0];
    const int*   dst = (const int*)d_in[1];
    const int*   n2g = (const int*)d_in[2];
    const float* W0  = (const float*)d_in[3];
    const float* b0  = (const float*)d_in[4];
    const float* W1  = (const float*)d_in[5];
    const float* b1  = (const float*)d_in[6];
    const float* W2  = (const float*)d_in[7];
    const float* b2  = (const float*)d_in[8];
    const float* Wr  = (const float*)d_in[9];
    const float* br  = (const float*)d_in[10];
    float* out = (float*)d_out;

    const int TB = 256;
    k_zero   <<<(N_NODES + TB - 1) / TB, TB>>>();
    k_deg    <<<(N_EDGES + TB - 1) / TB, TB>>>(src, dst);
    k_prep   <<<NBLK, CHUNK>>>();
    k_offsets<<<NBLK, CHUNK>>>();
    k_bucket <<<(N_EDGES + TB - 1) / TB, TB>>>(src, dst);
    k_xn     <<<(N_NODES + TB - 1) / TB, TB>>>();

    k_layer1 <<<(N_NODES + 7) / 8, TB>>>(W0, b0, W1, b1);
    k_layer2 <<<(N_NODES + 31) / 32, TB>>>(W2, b2);

    k_pool   <<<(POOL_WARPS * 32 + TB - 1) / TB, TB>>>(n2g);
    k_out    <<<(N_GRAPHS * 32 + TB - 1) / TB, TB>>>(Wr, br, out);
}

// round 17
// speedup vs baseline: 1.0522x; 1.0522x over previous
#include <cuda_runtime.h>

#define N_NODES  50000
#define N_EDGES  800000
#define N_GRAPHS 64
#define HID      64

#define CHUNK 256
#define NBLK ((N_NODES + CHUNK - 1) / CHUNK)   // 196

// ---------------- scratch (device globals; no allocation) ----------------
__device__ int    g_in_deg[N_NODES];
__device__ int    g_out_deg[N_NODES];
__device__ float  g_norm_src[N_NODES];
__device__ float  g_norm_dst[N_NODES];
__device__ float  g_h0n[N_NODES];         // in_deg * norm_src
__device__ float2 g_xn[N_NODES];          // (x0_v * nd_v * ns_v, ns_v)
__device__ int    g_row_off[N_NODES + 1];
__device__ int    g_cursor[N_NODES];
__device__ int    g_edge_src[N_EDGES];
__device__ float  g_hA[N_NODES * HID];    // layer-2 output
__device__ float  g_hB[N_NODES * HID];    // layer-1 output, pre-scaled by norm_src
__device__ float  g_hg[N_GRAPHS * HID];
__device__ float  g_cnt[N_GRAPHS];
__device__ int    g_blocksum[NBLK];       // lookback: block aggregates
__device__ int    g_flag[NBLK];           // lookback: 0 = not ready, 1 = aggregate ready

// ---------------- init ----------------
__global__ void k_zero() {
    int i = blockIdx.x * blockDim.x + threadIdx.x;
    if (i < N_NODES) { g_in_deg[i] = 0; g_out_deg[i] = 0; }
    if (i < N_GRAPHS * HID) g_hg[i] = 0.f;
    if (i < N_GRAPHS) g_cnt[i] = 0.f;
    if (i < NBLK) g_flag[i] = 0;
}

__global__ void k_deg(const int* __restrict__ src, const int* __restrict__ dst) {
    int i = blockIdx.x * blockDim.x + threadIdx.x;
    if (i < N_EDGES) {
        atomicAdd(&g_in_deg[dst[i]], 1);
        atomicAdd(&g_out_deg[src[i]], 1);
    }
}

// ---------------- fused prep + single-pass decoupled-lookback scan ----------------
// norms + h0n + exclusive scan of in_deg -> row_off/cursor, one launch.
// All NBLK=196 blocks are co-resident, so polling predecessors cannot deadlock.
__global__ void k_scan1() {
    __shared__ int s[CHUNK];
    __shared__ int sp[CHUNK];
    int t = threadIdx.x;
    int bid = blockIdx.x;
    int idx = bid * CHUNK + t;

    int my = 0;
    if (idx < N_NODES) {
        my = g_in_deg[idx];
        int od = g_out_deg[idx];
        float ns = rsqrtf((float)(od > 1 ? od : 1));
        g_norm_dst[idx] = rsqrtf((float)(my > 1 ? my : 1));
        g_norm_src[idx] = ns;
        g_h0n[idx] = (float)my * ns;
    }

    // local inclusive scan
    s[t] = my;
    __syncthreads();
    #pragma unroll
    for (int off = 1; off < CHUNK; off <<= 1) {
        int v = (t >= off) ? s[t - off] : 0;
        __syncthreads();
        s[t] += v;
        __syncthreads();
    }

    // publish this block's aggregate
    if (t == 0) {
        g_blocksum[bid] = s[CHUNK - 1];
        __threadfence();
        *((volatile int*)&g_flag[bid]) = 1;
    }

    // lookback: lane t polls predecessor t (bid <= 195 < 256)
    int contrib = 0;
    if (t < bid) {
        while (*((volatile int*)&g_flag[t]) == 0) { }
        __threadfence();
        contrib = g_blocksum[t];
    }
    sp[t] = contrib;
    __syncthreads();
    #pragma unroll
    for (int off = CHUNK / 2; off > 0; off >>= 1) {
        if (t < off) sp[t] += sp[t + off];
        __syncthreads();
    }
    int blockpre = sp[0];

    if (idx < N_NODES) {
        int ex = s[t] - my + blockpre;   // exclusive prefix
        g_row_off[idx] = ex;
        g_cursor[idx]  = ex;
    }
    if (idx == 0) g_row_off[N_NODES] = N_EDGES;
}

// ---------------- bucket edges by dst ----------------
__global__ void k_bucket(const int* __restrict__ src, const int* __restrict__ dst) {
    int i = blockIdx.x * blockDim.x + threadIdx.x;
    if (i < N_EDGES) {
        int d = dst[i];
        int p = atomicAdd(&g_cursor[d], 1);
        g_edge_src[p] = src[i];
    }
}

// ---------------- layer 0 (rank-1): scalar aggregate -> (x*ns, ns) pair ----------------
__global__ void k_x0() {
    int gtid = blockIdx.x * blockDim.x + threadIdx.x;
    int v = gtid >> 5;
    int lane = gtid & 31;
    if (v >= N_NODES) return;

    int beg = g_row_off[v], end = g_row_off[v + 1];
    float acc = 0.f;
    for (int e = beg + lane; e < end; e += 32) {
        acc += g_h0n[g_edge_src[e]];
    }
    #pragma unroll
    for (int off = 16; off; off >>= 1) acc += __shfl_xor_sync(0xffffffffu, acc, off);

    if (lane == 0) {
        float x  = acc * g_norm_dst[v];
        float ns = g_norm_src[v];
        float2 p; p.x = x * ns; p.y = ns;
        g_xn[v] = p;
    }
}

// ---------------- layer 1: rank-1 on-the-fly gather + fused 64x64 matvec ----------------
__global__ void __launch_bounds__(256) k_layer1(const float* __restrict__ W0,
                                                const float* __restrict__ b0,
                                                const float* __restrict__ W1,
                                                const float* __restrict__ b1) {
    __shared__ float sW[HID * HID];
    __shared__ float sb[HID];
    __shared__ float xs[8][HID];

    int tid = threadIdx.x;
    for (int i = tid; i < HID * HID; i += 256) sW[i] = W1[i];
    if (tid < HID) sb[tid] = b1[tid];
    __syncthreads();

    int wib = tid >> 5;
    int lane = tid & 31;
    int v = blockIdx.x * 8 + wib;

    float w0a = W0[2 * lane], w0b = W0[2 * lane + 1];
    float b0a = b0[2 * lane], b0b = b0[2 * lane + 1];

    if (v < N_NODES) {
        int beg = g_row_off[v], end = g_row_off[v + 1];
        float a0 = 0.f, a1 = 0.f;
        int e = beg;
        for (; e + 4 <= end; e += 4) {
            int s0 = g_edge_src[e];
            int s1 = g_edge_src[e + 1];
            int s2 = g_edge_src[e + 2];
            int s3 = g_edge_src[e + 3];
            float2 p0 = g_xn[s0];
            float2 p1 = g_xn[s1];
            float2 p2 = g_xn[s2];
            float2 p3 = g_xn[s3];
            a0 += fmaxf(fmaf(p0.x, w0a, b0a * p0.y), 0.f)
                + fmaxf(fmaf(p1.x, w0a, b0a * p1.y), 0.f)
                + fmaxf(fmaf(p2.x, w0a, b0a * p2.y), 0.f)
                + fmaxf(fmaf(p3.x, w0a, b0a * p3.y), 0.f);
            a1 += fmaxf(fmaf(p0.x, w0b, b0b * p0.y), 0.f)
                + fmaxf(fmaf(p1.x, w0b, b0b * p1.y), 0.f)
                + fmaxf(fmaf(p2.x, w0b, b0b * p2.y), 0.f)
                + fmaxf(fmaf(p3.x, w0b, b0b * p3.y), 0.f);
        }
        for (; e < end; e++) {
            float2 p = g_xn[g_edge_src[e]];
            a0 += fmaxf(fmaf(p.x, w0a, b0a * p.y), 0.f);
            a1 += fmaxf(fmaf(p.x, w0b, b0b * p.y), 0.f);
        }
        float nd = g_norm_dst[v];
        xs[wib][2 * lane]     = a0 * nd;
        xs[wib][2 * lane + 1] = a1 * nd;
    }
    __syncwarp();

    if (v < N_NODES) {
        float o0 = sb[2 * lane], o1 = sb[2 * lane + 1];
        #pragma unroll
        for (int i = 0; i < HID; i++) {
            float xi = xs[wib][i];
            float2 w = *(const float2*)&sW[i * HID + 2 * lane];
            o0 = fmaf(xi, w.x, o0);
            o1 = fmaf(xi, w.y, o1);
        }
        float ns = g_norm_src[v];           // pre-scale for layer 2
        float2 o;
        o.x = fmaxf(o0, 0.f) * ns;
        o.y = fmaxf(o1, 0.f) * ns;
        *(float2*)&g_hB[v * HID + 2 * lane] = o;
    }
}

// ---------------- layer 2: half-warp-per-node float4 gather + fused matvec ----------------
__global__ void __launch_bounds__(256) k_layer2(const float* __restrict__ W2,
                                                const float* __restrict__ b2) {
    __shared__ float sW[HID * HID];
    __shared__ float sb[HID];
    __shared__ float xs[16][HID];

    int tid = threadIdx.x;
    for (int i = tid; i < HID * HID; i += 256) sW[i] = W2[i];
    if (tid < HID) sb[tid] = b2[tid];
    __syncthreads();

    int hw  = tid >> 4;        // half-warp id in block: 0..15
    int sub = tid & 15;        // lane in half-warp
    int v = blockIdx.x * 16 + hw;

    if (v < N_NODES) {
        int beg = g_row_off[v], end = g_row_off[v + 1];
        float4 a = make_float4(0.f, 0.f, 0.f, 0.f);
        int e = beg;
        for (; e + 4 <= end; e += 4) {
            int s0 = g_edge_src[e];
            int s1 = g_edge_src[e + 1];
            int s2 = g_edge_src[e + 2];
            int s3 = g_edge_src[e + 3];
            float4 h0 = *(const float4*)&g_hB[s0 * HID + 4 * sub];
            float4 h1 = *(const float4*)&g_hB[s1 * HID + 4 * sub];
            float4 h2 = *(const float4*)&g_hB[s2 * HID + 4 * sub];
            float4 h3 = *(const float4*)&g_hB[s3 * HID + 4 * sub];
            a.x += (h0.x + h1.x) + (h2.x + h3.x);
            a.y += (h0.y + h1.y) + (h2.y + h3.y);
            a.z += (h0.z + h1.z) + (h2.z + h3.z);
            a.w += (h0.w + h1.w) + (h2.w + h3.w);
        }
        for (; e < end; e++) {
            int s = g_edge_src[e];
            float4 hv = *(const float4*)&g_hB[s * HID + 4 * sub];
            a.x += hv.x; a.y += hv.y; a.z += hv.z; a.w += hv.w;
        }
        float nd = g_norm_dst[v];
        a.x *= nd; a.y *= nd; a.z *= nd; a.w *= nd;
        *(float4*)&xs[hw][4 * sub] = a;
    }
    __syncwarp();

    if (v < N_NODES) {
        float4 o = *(const float4*)&sb[4 * sub];
        #pragma unroll
        for (int i = 0; i < HID; i++) {
            float xi = xs[hw][i];
            float4 w = *(const float4*)&sW[i * HID + 4 * sub];
            o.x = fmaf(xi, w.x, o.x);
            o.y = fmaf(xi, w.y, o.y);
            o.z = fmaf(xi, w.z, o.z);
            o.w = fmaf(xi, w.w, o.w);
        }
        o.x = fmaxf(o.x, 0.f);
        o.y = fmaxf(o.y, 0.f);
        o.z = fmaxf(o.z, 0.f);
        o.w = fmaxf(o.w, 0.f);
        *(float4*)&g_hA[v * HID + 4 * sub] = o;
    }
}

// ---------------- graph pooling: sorted node2graph run-length flush ----------------
#define NODES_PER_WARP 64
#define POOL_WARPS ((N_NODES + NODES_PER_WARP - 1) / NODES_PER_WARP)   // 782

__global__ void k_pool(const int* __restrict__ n2g) {
    int gtid = blockIdx.x * blockDim.x + threadIdx.x;
    int w = gtid >> 5;
    int lane = gtid & 31;
    if (w >= POOL_WARPS) return;

    int v0 = w * NODES_PER_WARP;
    int v1 = v0 + NODES_PER_WARP; if (v1 > N_NODES) v1 = N_NODES;

    int   cur = n2g[v0];
    float a0 = 0.f, a1 = 0.f;
    float cnt = 0.f;

    for (int v = v0; v < v1; v++) {
        int g = n2g[v];
        if (g != cur) {
            atomicAdd(&g_hg[cur * HID + 2 * lane],     a0);
            atomicAdd(&g_hg[cur * HID + 2 * lane + 1], a1);
            if (lane == 0) atomicAdd(&g_cnt[cur], cnt);
            cur = g; a0 = 0.f; a1 = 0.f; cnt = 0.f;
        }
        float2 hv = *(const float2*)&g_hA[v * HID + 2 * lane];
        a0 += hv.x;
        a1 += hv.y;
        cnt += 1.f;
    }
    atomicAdd(&g_hg[cur * HID + 2 * lane],     a0);
    atomicAdd(&g_hg[cur * HID + 2 * lane + 1], a1);
    if (lane == 0) atomicAdd(&g_cnt[cur], cnt);
}

// ---------------- readout ----------------
__global__ void k_out(const float* __restrict__ Wr, const float* __restrict__ br,
                      float* __restrict__ out) {
    int gtid = blockIdx.x * blockDim.x + threadIdx.x;
    int g = gtid >> 5;
    int lane = gtid & 31;
    if (g >= N_GRAPHS) return;
    float inv = 1.f / fmaxf(g_cnt[g], 1.f);
    float2 hv = *(const float2*)&g_hg[g * HID + 2 * lane];
    float2 wr = *(const float2*)&Wr[2 * lane];
    float acc = hv.x * inv * wr.x + hv.y * inv * wr.y;
    #pragma unroll
    for (int off = 16; off; off >>= 1) acc += __shfl_xor_sync(0xffffffffu, acc, off);
    if (lane == 0) out[g] = acc + br[0];
}

// ---------------- launch ----------------
extern "C" void kernel_launch(void* const* d_in, const int* in_sizes, int n_in,
                              void* d_out, int out_size) {
    const int*   src = (const int*)d_in[0];
    const int*   dst = (const int*)d_in[1];
    const int*   n2g = (const int*)d_in[2];
    const float* W0  = (const float*)d_in[3];
    const float* b0  = (const float*)d_in[4];
    const float* W1  = (const float*)d_in[5];
    const float* b1  = (const float*)d_in[6];
    const float* W2  = (const float*)d_in[7];
    const float* b2  = (const float*)d_in[8];
    const float* Wr  = (const float*)d_in[9];
    const float* br  = (const float*)d_in[10];
    float* out = (float*)d_out;

    const int TB = 256;
    k_zero   <<<(N_NODES + TB - 1) / TB, TB>>>();            // launch 1
    k_deg    <<<(N_EDGES + TB - 1) / TB, TB>>>(src, dst);    // launch 2
    k_scan1  <<<NBLK, CHUNK>>>();                            // launch 3 (prep+offsets fused)
    k_bucket <<<(N_EDGES + TB - 1) / TB, TB>>>(src, dst);    // launch 4  <- ncu slot

    k_x0     <<<(N_NODES * 32 + TB - 1) / TB, TB>>>();
    k_layer1 <<<(N_NODES + 7) / 8, TB>>>(W0, b0, W1, b1);
    k_layer2 <<<(N_NODES + 15) / 16, TB>>>(W2, b2);

    k_pool   <<<(POOL_WARPS * 32 + TB - 1) / TB, TB>>>(n2g);
    k_out    <<<(N_GRAPHS * 32 + TB - 1) / TB, TB>>>(Wr, br, out);
}